// round 3
// baseline (speedup 1.0000x reference)
#include <cuda_runtime.h>
#include <math.h>

#define E    4096
#define H    32
#define D    128
#define PAST 8191
#define KTOT 8192
#define NCHUNK 256
#define CHUNK  32

// GEMV tiling: 256 threads * float4 = 1024 cols per block, 32 rows per segment
#define GB_COLS 1024
#define GB_ROWS 32

// ---- device scratch (no allocations allowed) ----
__device__ float g_q[E];              // query (biased) after GEMV
__device__ float g_kv[2 * D];         // [key_new | value_new]
__device__ float g_m[NCHUNK * H];     // per-chunk per-head running max
__device__ float g_l[NCHUNK * H];     // per-chunk per-head exp sum
__device__ float g_po[(size_t)NCHUNK * H * D]; // per-chunk unnormalized output
__device__ float g_attn[E];           // merged attention output (h*D + d)

// ---------------------------------------------------------------------------
__global__ void init_kernel(const float* __restrict__ qb,
                            const float* __restrict__ kvb) {
    int t = blockIdx.x * blockDim.x + threadIdx.x;
    if (t < E) g_q[t] = qb[t];
    if (t < 2 * D) g_kv[t] = kvb[t];
}

// ---------------------------------------------------------------------------
// GEMV: out[j] += sum_i x[i] * W[i*ncols + j]
// grid = (ceil(ncols/1024), nrows/32), 256 threads
// ---------------------------------------------------------------------------
__global__ void gemv_atomic(const float* __restrict__ x,
                            const float* __restrict__ W,
                            float* __restrict__ out,
                            int ncols) {
    __shared__ float xs[GB_ROWS];
    const int i0 = blockIdx.y * GB_ROWS;
    if (threadIdx.x < GB_ROWS) xs[threadIdx.x] = x[i0 + threadIdx.x];
    __syncthreads();

    int j = blockIdx.x * GB_COLS + threadIdx.x * 4;
    if (j >= ncols) return;

    const float* wp = W + (size_t)i0 * ncols + j;
    float a0 = 0.f, a1 = 0.f, a2 = 0.f, a3 = 0.f;
#pragma unroll 16
    for (int i = 0; i < GB_ROWS; i++) {
        float4 w = __ldg((const float4*)(wp + (size_t)i * ncols));
        float xv = xs[i];
        a0 += xv * w.x; a1 += xv * w.y; a2 += xv * w.z; a3 += xv * w.w;
    }
    atomicAdd(&out[j + 0], a0);
    atomicAdd(&out[j + 1], a1);
    atomicAdd(&out[j + 2], a2);
    atomicAdd(&out[j + 3], a3);
}

// ---------------------------------------------------------------------------
// Split-K attention partial: one block per 32-key chunk, 256 threads,
// 256 blocks -> 2 resident blocks/SM so phases interleave across blocks.
// Dynamic smem layout (floats):
//   qs [E]          scaled q (h*D + d)          16 KB
//   ks [D*CHUNK]    K tile  (d*32 + k)          16 KB
//   vs [CHUNK*D]    V tile  (k*128 + d)         16 KB
//   ss [H*CHUNK]    scores -> exp weights        4 KB
// ---------------------------------------------------------------------------
__global__ void attn_partial(const float* __restrict__ pk,   // (D, PAST) d-major
                             const float* __restrict__ pv,   // (PAST, D) k-major
                             const float* __restrict__ mask) // (KTOT)
{
    extern __shared__ float smem[];
    float* qs = smem;                          // E
    float* ks = smem + E;                      // D*CHUNK
    float* vs = smem + E + D * CHUNK;          // CHUNK*D
    float* ss = smem + E + 2 * D * CHUNK;      // H*CHUNK

    const int t = threadIdx.x;
    const int kbase = blockIdx.x * CHUNK;
    const float scale = 0.088388347648318447f; // 1/sqrt(128)

    // load scaled q (4 float4 per thread)
    for (int i = t * 4; i < E; i += 256 * 4) {
        float4 v = *(const float4*)&g_q[i];
        v.x *= scale; v.y *= scale; v.z *= scale; v.w *= scale;
        *(float4*)&qs[i] = v;
    }

    // load K tile: ks[d*32 + k] = K[d, kbase+k]  (warp reads 32 contiguous k)
    for (int idx = t; idx < D * CHUNK; idx += 256) {
        int d = idx >> 5;
        int k = idx & 31;
        int kg = kbase + k;
        ks[idx] = (kg < PAST) ? pk[(size_t)d * PAST + kg] : g_kv[d];
    }
    __syncthreads();

    // ---- score phase: lane k = t&31, group hq = t>>5 owns 4 heads ----
    {
        const int k  = t & 31;
        const int hq = t >> 5;             // 0..7
        float a0 = 0.f, a1 = 0.f, a2 = 0.f, a3 = 0.f;

#pragma unroll 8
        for (int d4 = 0; d4 < D / 4; d4++) {
            const int d = d4 * 4;
            float k0 = ks[(d + 0) * CHUNK + k];
            float k1 = ks[(d + 1) * CHUNK + k];
            float k2 = ks[(d + 2) * CHUNK + k];
            float k3 = ks[(d + 3) * CHUNK + k];
            float4 q0 = *(const float4*)&qs[(hq * 4 + 0) * D + d];
            float4 q1 = *(const float4*)&qs[(hq * 4 + 1) * D + d];
            float4 q2 = *(const float4*)&qs[(hq * 4 + 2) * D + d];
            float4 q3 = *(const float4*)&qs[(hq * 4 + 3) * D + d];
            a0 += q0.x * k0 + q0.y * k1 + q0.z * k2 + q0.w * k3;
            a1 += q1.x * k0 + q1.y * k1 + q1.z * k2 + q1.w * k3;
            a2 += q2.x * k0 + q2.y * k1 + q2.z * k2 + q2.w * k3;
            a3 += q3.x * k0 + q3.y * k1 + q3.z * k2 + q3.w * k3;
        }
        float mk = mask[kbase + k];
        ss[(hq * 4 + 0) * CHUNK + k] = a0 + mk;
        ss[(hq * 4 + 1) * CHUNK + k] = a1 + mk;
        ss[(hq * 4 + 2) * CHUNK + k] = a2 + mk;
        ss[(hq * 4 + 3) * CHUNK + k] = a3 + mk;
    }
    __syncthreads();

    // ---- load V tile (independent of softmax; overlaps with it) ----
    for (int idx = t; idx < CHUNK * D; idx += 256) {
        int k = idx >> 7;
        int d = idx & 127;
        int kg = kbase + k;
        vs[idx] = (kg < PAST) ? pv[(size_t)kg * D + d] : g_kv[D + d];
    }

    // ---- softmax: 8 lanes per head, 4 keys each, shuffle reduce ----
    {
        const int h = t >> 3;          // 0..31
        const int j = (t & 7) * 4;     // key quad base
        float4 s = *(const float4*)&ss[h * CHUNK + j];
        float m = fmaxf(fmaxf(s.x, s.y), fmaxf(s.z, s.w));
        m = fmaxf(m, __shfl_xor_sync(0xffffffff, m, 1));
        m = fmaxf(m, __shfl_xor_sync(0xffffffff, m, 2));
        m = fmaxf(m, __shfl_xor_sync(0xffffffff, m, 4));
        s.x = __expf(s.x - m); s.y = __expf(s.y - m);
        s.z = __expf(s.z - m); s.w = __expf(s.w - m);
        float l = s.x + s.y + s.z + s.w;
        l += __shfl_xor_sync(0xffffffff, l, 1);
        l += __shfl_xor_sync(0xffffffff, l, 2);
        l += __shfl_xor_sync(0xffffffff, l, 4);
        *(float4*)&ss[h * CHUNK + j] = s;
        if ((t & 7) == 0) {
            g_m[blockIdx.x * H + h] = m;
            g_l[blockIdx.x * H + h] = l;
        }
    }
    __syncthreads();

    // ---- V phase: d = t&127, half hh = t>>7 owns 16 heads ----
    {
        const int d  = t & 127;
        const int hh = (t >> 7) * 16;  // 0 or 16
        float o[16];
#pragma unroll
        for (int h = 0; h < 16; h++) o[h] = 0.f;

#pragma unroll 4
        for (int j4 = 0; j4 < CHUNK / 4; j4++) {
            const int j = j4 * 4;
            float v0 = vs[(j + 0) * D + d];
            float v1 = vs[(j + 1) * D + d];
            float v2 = vs[(j + 2) * D + d];
            float v3 = vs[(j + 3) * D + d];
#pragma unroll
            for (int h = 0; h < 16; h++) {
                float4 w = *(const float4*)&ss[(hh + h) * CHUNK + j];
                o[h] += w.x * v0 + w.y * v1 + w.z * v2 + w.w * v3;
            }
        }
#pragma unroll
        for (int h = 0; h < 16; h++)
            g_po[((size_t)blockIdx.x * H + hh + h) * D + d] = o[h];
    }
}

// ---------------------------------------------------------------------------
// Combine partials (blocks 0..31 = heads, 128 threads = d).
// Block 32: initialize d_out with proj bias + write key_perm / value_new tail.
// ---------------------------------------------------------------------------
__global__ void combine_kernel(const float* __restrict__ proj_b,
                               float* __restrict__ out) {
    if (blockIdx.x == H) {
        for (int j = threadIdx.x; j < E; j += blockDim.x) out[j] = proj_b[j];
        if (threadIdx.x < D) {
            out[E + threadIdx.x]     = g_kv[threadIdx.x];       // key_perm
            out[E + D + threadIdx.x] = g_kv[D + threadIdx.x];   // value_new
        }
        return;
    }
    const int h = blockIdx.x;
    const int d = threadIdx.x;

    float m = -1e30f;
#pragma unroll 16
    for (int c = 0; c < NCHUNK; c++) m = fmaxf(m, g_m[c * H + h]);

    float L = 0.f, o = 0.f;
#pragma unroll 8
    for (int c = 0; c < NCHUNK; c++) {
        float sc = __expf(g_m[c * H + h] - m);
        L += g_l[c * H + h] * sc;
        o += g_po[((size_t)c * H + h) * D + d] * sc;
    }
    g_attn[h * D + d] = o / L;
}

// ---------------------------------------------------------------------------
extern "C" void kernel_launch(void* const* d_in, const int* in_sizes, int n_in,
                              void* d_out, int out_size) {
    const float* hs   = (const float*)d_in[0];
    const float* pk   = (const float*)d_in[1];
    const float* pv   = (const float*)d_in[2];
    const float* mask = (const float*)d_in[3];
    const float* qw   = (const float*)d_in[4];
    const float* qb   = (const float*)d_in[5];
    const float* kvw  = (const float*)d_in[6];
    const float* kvb  = (const float*)d_in[7];
    const float* pw   = (const float*)d_in[8];
    const float* pb   = (const float*)d_in[9];
    float* out = (float*)d_out;

    float *gq = nullptr, *gkv = nullptr, *gattn = nullptr;
    cudaGetSymbolAddress((void**)&gq,    g_q);
    cudaGetSymbolAddress((void**)&gkv,   g_kv);
    cudaGetSymbolAddress((void**)&gattn, g_attn);

    const int attn_smem = (E + 2 * D * CHUNK + H * CHUNK) * (int)sizeof(float); // 52 KB
    static int smem_set = 0;
    if (!smem_set) {
        cudaFuncSetAttribute(attn_partial,
                             cudaFuncAttributeMaxDynamicSharedMemorySize,
                             attn_smem);
        smem_set = 1;
    }

    // 1) seed biases (resets accumulators every replay)
    init_kernel<<<16, 256>>>(qb, kvb);

    // 2) q = h @ q_w + q_b   (grid 4x128 = 512 blocks)
    gemv_atomic<<<dim3(4, 128), 256>>>(hs, qw, gq, E);

    // 3) kv = h @ kv_w + kv_b (grid 1x128)
    gemv_atomic<<<dim3(1, 128), 256>>>(hs, kvw, gkv, 2 * D);

    // 4) split-K attention partials (256 chunks of 32 keys)
    attn_partial<<<NCHUNK, 256, attn_smem>>>(pk, pv, mask);

    // 5) merge partials; init output with proj bias; write kv outputs
    combine_kernel<<<H + 1, 128>>>(pb, out);

    // 6) out[0:4096] += attn @ proj_w
    gemv_atomic<<<dim3(4, 128), 256>>>(gattn, pw, out, E);
}

// round 4
// speedup vs baseline: 1.0644x; 1.0644x over previous
#include <cuda_runtime.h>
#include <math.h>

#define E    4096
#define H    32
#define D    128
#define PAST 8191
#define KTOT 8192
#define NCHUNK 256
#define CHUNK  32

// GEMV tiling: 256 threads * float4 = 1024 cols per block, 32 rows per segment
#define GB_COLS 1024
#define GB_ROWS 32

// ---- device scratch (no allocations allowed) ----
__device__ float g_q[E];              // query (biased) after GEMV
__device__ float g_kv[2 * D];         // [key_new | value_new]
__device__ float g_m[NCHUNK * H];     // per-chunk per-head running max
__device__ float g_l[NCHUNK * H];     // per-chunk per-head exp sum
__device__ float g_po[(size_t)NCHUNK * H * D]; // per-chunk unnormalized output
__device__ float g_attn[E];           // merged attention output (h*D + d)

// ---------------------------------------------------------------------------
__global__ void init_kernel(const float* __restrict__ qb,
                            const float* __restrict__ kvb) {
    int t = blockIdx.x * blockDim.x + threadIdx.x;
    if (t < E) g_q[t] = qb[t];
    if (t < 2 * D) g_kv[t] = kvb[t];
}

// ---------------------------------------------------------------------------
// GEMV: out[j] += sum_i x[i] * W[i*ncols + j]   (R2 form — do not touch)
// grid = (ceil(ncols/1024), nrows/32), 256 threads
// ---------------------------------------------------------------------------
__global__ void gemv_atomic(const float* __restrict__ x,
                            const float* __restrict__ W,
                            float* __restrict__ out,
                            int ncols) {
    __shared__ float xs[GB_ROWS];
    const int i0 = blockIdx.y * GB_ROWS;
    if (threadIdx.x < GB_ROWS) xs[threadIdx.x] = x[i0 + threadIdx.x];
    __syncthreads();

    int j = blockIdx.x * GB_COLS + threadIdx.x * 4;
    if (j >= ncols) return;

    const float* wp = W + (size_t)i0 * ncols + j;
    float a0 = 0.f, a1 = 0.f, a2 = 0.f, a3 = 0.f;
#pragma unroll 8
    for (int i = 0; i < GB_ROWS; i++) {
        float4 w = *(const float4*)(wp + (size_t)i * ncols);
        float xv = xs[i];
        a0 += xv * w.x; a1 += xv * w.y; a2 += xv * w.z; a3 += xv * w.w;
    }
    atomicAdd(&out[j + 0], a0);
    atomicAdd(&out[j + 1], a1);
    atomicAdd(&out[j + 2], a2);
    atomicAdd(&out[j + 3], a3);
}

// ---------------------------------------------------------------------------
// Split-K attention partial v4: 256 blocks x 128 threads, 32 keys per block.
// K and V streamed DIRECTLY from GMEM (coalesced); only q + scores in smem.
// ---------------------------------------------------------------------------
__global__ void __launch_bounds__(128)
attn_partial(const float* __restrict__ pk,   // (D, PAST) d-major
             const float* __restrict__ pv,   // (PAST, D) k-major
             const float* __restrict__ mask) // (KTOT)
{
    __shared__ float qs[E];          // scaled q (h*D + d)      16 KB
    __shared__ float ss[H * CHUNK];  // scores -> weights        4 KB

    const int t = threadIdx.x;
    const int kbase = blockIdx.x * CHUNK;
    const float scale = 0.088388347648318447f; // 1/sqrt(128)

    // load scaled q: 8 float4 per thread
#pragma unroll
    for (int i = t * 4; i < E; i += 128 * 4) {
        float4 v = *(const float4*)&g_q[i];
        v.x *= scale; v.y *= scale; v.z *= scale; v.w *= scale;
        *(float4*)&qs[i] = v;
    }
    __syncthreads();

    // ---- score phase: lane = key, warp w owns heads w*8..w*8+7 ----
    {
        const int lane = t & 31;
        const int w = t >> 5;
        const int kg = kbase + lane;

        const float* kp; int kstr;
        if (kg < PAST) { kp = pk + kg; kstr = PAST; }
        else           { kp = g_kv;   kstr = 1;    }

        float acc[8];
#pragma unroll
        for (int h = 0; h < 8; h++) acc[h] = 0.f;

#pragma unroll 8
        for (int d4 = 0; d4 < D / 4; d4++) {
            const int d = d4 * 4;
            float k0 = kp[(size_t)(d + 0) * kstr];
            float k1 = kp[(size_t)(d + 1) * kstr];
            float k2 = kp[(size_t)(d + 2) * kstr];
            float k3 = kp[(size_t)(d + 3) * kstr];
#pragma unroll
            for (int h = 0; h < 8; h++) {
                float4 qv = *(const float4*)&qs[(w * 8 + h) * D + d];
                acc[h] += qv.x * k0 + qv.y * k1 + qv.z * k2 + qv.w * k3;
            }
        }
        float mk = mask[kg];
#pragma unroll
        for (int h = 0; h < 8; h++) ss[(w * 8 + h) * CHUNK + lane] = acc[h] + mk;
    }
    __syncthreads();

    // ---- softmax: 4 threads per head (8 keys each), shuffle reduce ----
    {
        const int h = t >> 2;          // 0..31
        const int j = (t & 3) * 8;     // key octet base
        float4 s0 = *(const float4*)&ss[h * CHUNK + j];
        float4 s1 = *(const float4*)&ss[h * CHUNK + j + 4];
        float m = fmaxf(fmaxf(fmaxf(s0.x, s0.y), fmaxf(s0.z, s0.w)),
                        fmaxf(fmaxf(s1.x, s1.y), fmaxf(s1.z, s1.w)));
        m = fmaxf(m, __shfl_xor_sync(0xffffffff, m, 1));
        m = fmaxf(m, __shfl_xor_sync(0xffffffff, m, 2));
        s0.x = __expf(s0.x - m); s0.y = __expf(s0.y - m);
        s0.z = __expf(s0.z - m); s0.w = __expf(s0.w - m);
        s1.x = __expf(s1.x - m); s1.y = __expf(s1.y - m);
        s1.z = __expf(s1.z - m); s1.w = __expf(s1.w - m);
        float l = s0.x + s0.y + s0.z + s0.w + s1.x + s1.y + s1.z + s1.w;
        l += __shfl_xor_sync(0xffffffff, l, 1);
        l += __shfl_xor_sync(0xffffffff, l, 2);
        *(float4*)&ss[h * CHUNK + j]     = s0;
        *(float4*)&ss[h * CHUNK + j + 4] = s1;
        if ((t & 3) == 0) {
            g_m[blockIdx.x * H + h] = m;
            g_l[blockIdx.x * H + h] = l;
        }
    }
    __syncthreads();

    // ---- AV phase: thread = d (0..127), 32 head accumulators ----
    {
        float o[H];
#pragma unroll
        for (int h = 0; h < H; h++) o[h] = 0.f;

#pragma unroll 2
        for (int k4 = 0; k4 < CHUNK / 4; k4++) {
            const int k = k4 * 4;
            const int kg0 = kbase + k;
            const float* v0p = (kg0 + 0 < PAST) ? pv + (size_t)(kg0 + 0) * D : g_kv + D;
            const float* v1p = (kg0 + 1 < PAST) ? pv + (size_t)(kg0 + 1) * D : g_kv + D;
            const float* v2p = (kg0 + 2 < PAST) ? pv + (size_t)(kg0 + 2) * D : g_kv + D;
            const float* v3p = (kg0 + 3 < PAST) ? pv + (size_t)(kg0 + 3) * D : g_kv + D;
            float v0 = v0p[t];
            float v1 = v1p[t];
            float v2 = v2p[t];
            float v3 = v3p[t];
#pragma unroll
            for (int h = 0; h < H; h++) {
                float4 wv = *(const float4*)&ss[h * CHUNK + k];
                o[h] += wv.x * v0 + wv.y * v1 + wv.z * v2 + wv.w * v3;
            }
        }
#pragma unroll
        for (int h = 0; h < H; h++)
            g_po[((size_t)blockIdx.x * H + h) * D + t] = o[h];
    }
}

// ---------------------------------------------------------------------------
// Combine partials (blocks 0..31 = heads, 128 threads = d).
// Block 32: initialize d_out with proj bias + write key_perm / value_new tail.
// ---------------------------------------------------------------------------
__global__ void combine_kernel(const float* __restrict__ proj_b,
                               float* __restrict__ out) {
    if (blockIdx.x == H) {
        for (int j = threadIdx.x; j < E; j += blockDim.x) out[j] = proj_b[j];
        if (threadIdx.x < D) {
            out[E + threadIdx.x]     = g_kv[threadIdx.x];       // key_perm
            out[E + D + threadIdx.x] = g_kv[D + threadIdx.x];   // value_new
        }
        return;
    }
    const int h = blockIdx.x;
    const int d = threadIdx.x;

    float m = -1e30f;
#pragma unroll 16
    for (int c = 0; c < NCHUNK; c++) m = fmaxf(m, g_m[c * H + h]);

    float L = 0.f, o = 0.f;
#pragma unroll 8
    for (int c = 0; c < NCHUNK; c++) {
        float sc = __expf(g_m[c * H + h] - m);
        L += g_l[c * H + h] * sc;
        o += g_po[((size_t)c * H + h) * D + d] * sc;
    }
    g_attn[h * D + d] = o / L;
}

// ---------------------------------------------------------------------------
extern "C" void kernel_launch(void* const* d_in, const int* in_sizes, int n_in,
                              void* d_out, int out_size) {
    const float* hs   = (const float*)d_in[0];
    const float* pk   = (const float*)d_in[1];
    const float* pv   = (const float*)d_in[2];
    const float* mask = (const float*)d_in[3];
    const float* qw   = (const float*)d_in[4];
    const float* qb   = (const float*)d_in[5];
    const float* kvw  = (const float*)d_in[6];
    const float* kvb  = (const float*)d_in[7];
    const float* pw   = (const float*)d_in[8];
    const float* pb   = (const float*)d_in[9];
    float* out = (float*)d_out;

    float *gq = nullptr, *gkv = nullptr, *gattn = nullptr;
    cudaGetSymbolAddress((void**)&gq,    g_q);
    cudaGetSymbolAddress((void**)&gkv,   g_kv);
    cudaGetSymbolAddress((void**)&gattn, g_attn);

    // 1) seed biases (resets accumulators every replay)
    init_kernel<<<16, 256>>>(qb, kvb);

    // 2) q = h @ q_w + q_b   (grid 4x128 = 512 blocks)
    gemv_atomic<<<dim3(4, 128), 256>>>(hs, qw, gq, E);

    // 3) kv = h @ kv_w + kv_b (grid 1x128)
    gemv_atomic<<<dim3(1, 128), 256>>>(hs, kvw, gkv, 2 * D);

    // 4) split-K attention partials (256 chunks of 32 keys)
    attn_partial<<<NCHUNK, 128>>>(pk, pv, mask);

    // 5) merge partials; init output with proj bias; write kv outputs
    combine_kernel<<<H + 1, 128>>>(pb, out);

    // 6) out[0:4096] += attn @ proj_w
    gemv_atomic<<<dim3(4, 128), 256>>>(gattn, pw, out, E);
}